// round 15
// baseline (speedup 1.0000x reference)
#include <cuda_runtime.h>
#include <cuda_bf16.h>
#include <cuda_fp16.h>
#include <cstdint>
#include <math.h>

// Problem constants
#define NHEADS 16
#define HEADD  64
#define EMBED  1024
#define SEQ    2048
#define BATCH  4
#define BS     (BATCH*SEQ)          // 8192 rows
#define QKV_ELEMS (BATCH*NHEADS*SEQ*HEADD)  // 8388608
#define W_ELEMS (NHEADS*EMBED*HEADD)        // 1048576

#define CK     64                   // K-chunk for projection GEMMs
#define NC2    (EMBED/CK)           // 16 chunks

#define SRA    72                   // A smem row stride (halves): 64 data + 8 pad
#define SBN    136                  // B smem row stride (halves): 128 data + 8 pad

// Q pre-scale: 1/sqrt(64) * log2(e)  (softmax runs in log2 domain)
#define QSCALE 0.180336880111273336f

// Scratch (static device globals: allocation-free)
__device__ __half g_x16[BS*EMBED];          // x fp16
__device__ __half g_Wf[3*W_ELEMS];          // Wq|Wk|Wv fp16
__device__ __half g_Wo16[EMBED*EMBED];      // Wo fp16
__device__ __half g_Qh[QKV_ELEMS];          // Q hi (pre-scaled by QSCALE)
__device__ __half g_Ql[QKV_ELEMS];          // Q lo residual (pre-scaled)
__device__ __half g_K16[QKV_ELEMS];         // K fp16
__device__ __half g_V16[QKV_ELEMS];         // V fp16
__device__ __half g_C16[QKV_ELEMS];         // attn output fp16 [B,S,H*D]

// ---------------------------------------------------------------------------
// Common PTX helpers
// ---------------------------------------------------------------------------
__device__ __forceinline__ uint32_t smem_u32(const void* p) {
    uint32_t a;
    asm("{ .reg .u64 t; cvta.to.shared.u64 t, %1; cvt.u32.u64 %0, t; }" : "=r"(a) : "l"(p));
    return a;
}
__device__ __forceinline__ void ldmx4(uint32_t addr, uint32_t& r0, uint32_t& r1,
                                      uint32_t& r2, uint32_t& r3) {
    asm volatile("ldmatrix.sync.aligned.m8n8.x4.shared.b16 {%0,%1,%2,%3}, [%4];"
                 : "=r"(r0), "=r"(r1), "=r"(r2), "=r"(r3) : "r"(addr));
}
__device__ __forceinline__ void ldmx4t(uint32_t addr, uint32_t& r0, uint32_t& r1,
                                       uint32_t& r2, uint32_t& r3) {
    asm volatile("ldmatrix.sync.aligned.m8n8.x4.trans.shared.b16 {%0,%1,%2,%3}, [%4];"
                 : "=r"(r0), "=r"(r1), "=r"(r2), "=r"(r3) : "r"(addr));
}
__device__ __forceinline__ void mma_f16(float* d, const uint32_t* a, const uint32_t* b) {
    asm volatile(
        "mma.sync.aligned.m16n8k16.row.col.f32.f16.f16.f32 "
        "{%0,%1,%2,%3}, {%4,%5,%6,%7}, {%8,%9}, {%0,%1,%2,%3};"
        : "+f"(d[0]), "+f"(d[1]), "+f"(d[2]), "+f"(d[3])
        : "r"(a[0]), "r"(a[1]), "r"(a[2]), "r"(a[3]), "r"(b[0]), "r"(b[1]));
}
__device__ __forceinline__ void cpa16(uint32_t dst, const void* src) {
    asm volatile("cp.async.cg.shared.global [%0], [%1], 16;" :: "r"(dst), "l"(src) : "memory");
}
#define CPA_COMMIT() asm volatile("cp.async.commit_group;" ::: "memory")
#define CPA_WAIT0()  asm volatile("cp.async.wait_group 0;" ::: "memory")
#define CPA_WAIT1()  asm volatile("cp.async.wait_group 1;" ::: "memory")
__device__ __forceinline__ uint32_t h2u(__half2 v) { return *reinterpret_cast<uint32_t*>(&v); }

// ---------------------------------------------------------------------------
// Conversion kernel: z=0..3 -> weights; z=4..11 -> x segments. 2 float4/thread.
// ---------------------------------------------------------------------------
#define CONV_SEG 262144

__global__ __launch_bounds__(256) void conv_all_kernel(
    const float4* __restrict__ x,
    const float4* __restrict__ Wq, const float4* __restrict__ Wk,
    const float4* __restrict__ Wv, const float4* __restrict__ Wo,
    __half* __restrict__ dx, __half* __restrict__ dWf, __half* __restrict__ dWo)
{
    int z = blockIdx.y;
    int i0 = blockIdx.x * 256 + threadIdx.x;
    const float4* src;
    __half* dst;
    if (z < 4) {
        src = (z == 0) ? Wq : (z == 1) ? Wk : (z == 2) ? Wv : Wo;
        dst = (z < 3) ? (dWf + (size_t)z * W_ELEMS) : dWo;
    } else {
        size_t off = (size_t)(z - 4) * CONV_SEG;
        src = x + off;
        dst = dx + off * 4;
    }
    float4 v0 = src[i0];
    float4 v1 = src[i0 + CONV_SEG/2];
    *(uint2*)&dst[(size_t)i0*4] =
        make_uint2(h2u(__floats2half2_rn(v0.x, v0.y)), h2u(__floats2half2_rn(v0.z, v0.w)));
    *(uint2*)&dst[((size_t)i0 + CONV_SEG/2)*4] =
        make_uint2(h2u(__floats2half2_rn(v1.x, v1.y)), h2u(__floats2half2_rn(v1.z, v1.w)));
}

// ---------------------------------------------------------------------------
// Projection GEMM smem layout (CK=64)
// ---------------------------------------------------------------------------
#define ASZ2 (128*SRA*2)            // 18432
#define BSZ2 (64*SBN*2)             // 17408
#define BUF2 (ASZ2 + BSZ2)          // 35840
#define PROJ_SMEM (3*BUF2)          // 107520

// ---------------------------------------------------------------------------
// Kernel 1: fused QKV projection — fp16 single-pass, CK=64, 3-stage pipeline.
// ---------------------------------------------------------------------------
__global__ __launch_bounds__(256) void qkv_mma_kernel()
{
    extern __shared__ char smem[];
    const uint32_t sb = smem_u32(smem);
    const int tid = threadIdx.x;
    const int warp = tid >> 5, lane = tid & 31;
    const int wm = warp & 3, wn = warp >> 2;

    const int z  = blockIdx.z;
    const __half* Wf = g_Wf + (size_t)z * W_ELEMS;
    const int h0 = blockIdx.y * 2;
    const int m0 = blockIdx.x * 128;

    auto issue = [&](int c, int buf) {
        const uint32_t bb = sb + buf * BUF2;
        const int k0 = c * CK;
        #pragma unroll
        for (int i = 0; i < 4; i++) {
            int idx = i * 256 + tid;
            int q = idx & 7, m = idx >> 3;
            const __half* src = g_x16 + (size_t)(m0 + m) * EMBED + k0 + q * 8;
            cpa16(bb + (uint32_t)((m * SRA + q * 8) * 2), src);
        }
        #pragma unroll
        for (int i = 0; i < 4; i++) {
            int idx = i * 256 + tid;
            int seg = idx & 7, h1 = (idx >> 3) & 1, k = idx >> 4;
            const __half* src = Wf + ((size_t)(h0 + h1) * EMBED + k0 + k) * HEADD + seg * 8;
            cpa16(bb + ASZ2 + (uint32_t)((k * SBN + h1 * 64 + seg * 8) * 2), src);
        }
        CPA_COMMIT();
    };

    float acc[2][8][4] = {};
    const uint32_t aAoff = (uint32_t)(((wm*32 + (lane & 15)) * SRA + (lane >> 4) * 8) * 2);
    const uint32_t bBoff = (uint32_t)(((lane & 15) * SBN + (lane >> 4) * 8) * 2);

    issue(0, 0);
    issue(1, 1);
    int bufc = 0;
    for (int c = 0; c < NC2; c++) {
        CPA_WAIT1();
        __syncthreads();
        if (c + 2 < NC2) issue(c + 2, (c + 2) % 3); else CPA_COMMIT();

        const uint32_t bb = sb + bufc * BUF2;
        bufc = (bufc + 1) % 3;
        #pragma unroll
        for (int ks = 0; ks < 4; ks++) {
            const uint32_t kb = (uint32_t)(ks * 32);
            uint32_t ah[2][4], bf[4][4];
            #pragma unroll
            for (int mi = 0; mi < 2; mi++)
                ldmx4(bb + aAoff + mi*(16*SRA*2) + kb, ah[mi][0], ah[mi][1], ah[mi][2], ah[mi][3]);
            #pragma unroll
            for (int p = 0; p < 4; p++)
                ldmx4t(bb + ASZ2 + (uint32_t)((ks*16*SBN + wn*64 + p*16) * 2) + bBoff,
                       bf[p][0], bf[p][1], bf[p][2], bf[p][3]);
            #pragma unroll
            for (int mi = 0; mi < 2; mi++)
                #pragma unroll
                for (int nj = 0; nj < 8; nj++)
                    mma_f16(acc[mi][nj], ah[mi], &bf[nj >> 1][(nj & 1) * 2]);
        }
    }

    const int h = h0 + wn;
    #pragma unroll
    for (int mi = 0; mi < 2; mi++) {
        const int m = m0 + wm*32 + mi*16 + (lane >> 2);
        const int b = m >> 11, s = m & 2047;
        const size_t rowbase  = (((size_t)b * NHEADS + h) * SEQ + s) * HEADD;
        const size_t rowbase8 = rowbase + 8 * HEADD;
        #pragma unroll
        for (int nj = 0; nj < 8; nj++) {
            const int d = nj*8 + (lane & 3) * 2;
            float a0 = acc[mi][nj][0], a1 = acc[mi][nj][1];
            float a2 = acc[mi][nj][2], a3 = acc[mi][nj][3];
            if (z == 0) {
                a0 *= QSCALE; a1 *= QSCALE; a2 *= QSCALE; a3 *= QSCALE;
                __half2 h01 = __floats2half2_rn(a0, a1);
                __half2 h23 = __floats2half2_rn(a2, a3);
                float2 f01 = __half22float2(h01);
                float2 f23 = __half22float2(h23);
                __half2 l01 = __floats2half2_rn(a0 - f01.x, a1 - f01.y);
                __half2 l23 = __floats2half2_rn(a2 - f23.x, a3 - f23.y);
                *(uint32_t*)&g_Qh[rowbase  + d] = h2u(h01);
                *(uint32_t*)&g_Qh[rowbase8 + d] = h2u(h23);
                *(uint32_t*)&g_Ql[rowbase  + d] = h2u(l01);
                *(uint32_t*)&g_Ql[rowbase8 + d] = h2u(l23);
            } else if (z == 1) {
                *(uint32_t*)&g_K16[rowbase  + d] = h2u(__floats2half2_rn(a0, a1));
                *(uint32_t*)&g_K16[rowbase8 + d] = h2u(__floats2half2_rn(a2, a3));
            } else {
                *(uint32_t*)&g_V16[rowbase  + d] = h2u(__floats2half2_rn(a0, a1));
                *(uint32_t*)&g_V16[rowbase8 + d] = h2u(__floats2half2_rn(a2, a3));
            }
        }
    }
}

// ---------------------------------------------------------------------------
// Kernel 2: causal flash attention. 128-key TRANSFER chunks (one wait/sync per
// 128 keys), 64-key compute sub-tiles (register pressure unchanged).
// QK 2-pass, PV 1-pass, no-max softmax, Q-in-regs. 2 CTA/SM.
// ---------------------------------------------------------------------------
#define SRH 72
#define TSZ (128*SRH*2)             // one 128-row tile = 18432 B
#define ATTN_SMEM (6*TSZ)           // Qh,Ql + K0,K1,V0,V1 = 110592
#define OQH 0
#define OQL TSZ
#define OK0 (2*TSZ)
#define OK1 (3*TSZ)
#define OV0 (4*TSZ)
#define OV1 (5*TSZ)
#define SUBT (64*SRH*2)             // 64-row sub-tile stride = 9216 B

__global__ __launch_bounds__(256, 2) void attn_mma_kernel()
{
    extern __shared__ char smem[];
    const uint32_t sb = smem_u32(smem);

    const int it = (int)gridDim.x - 1 - (int)blockIdx.x;
    const int h  = blockIdx.y;
    const int b  = blockIdx.z;
    const size_t base = (((size_t)b * NHEADS + h) * SEQ) * HEADD;

    const int tid  = threadIdx.x;
    const int warp = tid >> 5, lane = tid & 31;
    const int q0 = it * 128;
    const int ntc = it + 1;                    // 128-key chunks

    // Prologue: Q hi/lo + chunk 0 K/V (128 rows each), one cp.async group
    {
        const __half* Qh = g_Qh + base + (size_t)q0 * HEADD;
        const __half* Ql = g_Ql + base + (size_t)q0 * HEADD;
        const __half* Kp = g_K16 + base;
        const __half* Vp = g_V16 + base;
        #pragma unroll
        for (int i = 0; i < 4; i++) {
            int c = tid + i * 256;             // 1024: 128 rows x 8 segs
            int row = c >> 3, cc = c & 7;
            uint32_t off = (uint32_t)((row*SRH + cc*8)*2);
            cpa16(sb + OQH + off, Qh + row*HEADD + cc*8);
            cpa16(sb + OQL + off, Ql + row*HEADD + cc*8);
            cpa16(sb + OK0 + off, Kp + row*HEADD + cc*8);
            cpa16(sb + OV0 + off, Vp + row*HEADD + cc*8);
        }
        CPA_COMMIT();
    }

    float oa[8][4] = {};
    float l0 = 0.0f, l1 = 0.0f;

    const uint32_t aQoff = (uint32_t)(((warp*16 + (lane & 15)) * SRH + (lane >> 4) * 8) * 2);
    const int j = lane >> 3;
    const uint32_t aBoff = (uint32_t)((((j >> 1) * 8 + (lane & 7)) * SRH + (j & 1) * 8) * 2);
    const uint32_t aVoff = (uint32_t)(((lane & 15) * SRH + (lane >> 4) * 8) * 2);
    const int rowmax = q0 + warp*16 + 15;

    // Hoist Q fragments into registers
    uint32_t qh[4][4], ql[4][4];
    {
        CPA_WAIT0();
        __syncthreads();
        #pragma unroll
        for (int ks = 0; ks < 4; ks++) {
            const uint32_t kb = (uint32_t)(ks * 16 * 2);
            ldmx4(sb + OQH + aQoff + kb, qh[ks][0], qh[ks][1], qh[ks][2], qh[ks][3]);
            ldmx4(sb + OQL + aQoff + kb, ql[ks][0], ql[ks][1], ql[ks][2], ql[ks][3]);
        }
    }

    for (int ktc = 0; ktc < ntc; ktc++) {
        if (ktc > 0) { CPA_WAIT0(); __syncthreads(); }
        const uint32_t bufK = (ktc & 1) ? OK1 : OK0;
        const uint32_t bufV = (ktc & 1) ? OV1 : OV0;

        // Prefetch next 128-key chunk
        if (ktc + 1 < ntc) {
            const int kn = (ktc + 1) * 128;
            const uint32_t nK = ((ktc + 1) & 1) ? OK1 : OK0;
            const uint32_t nV = ((ktc + 1) & 1) ? OV1 : OV0;
            const __half* Kp = g_K16 + base + (size_t)kn * HEADD;
            const __half* Vp = g_V16 + base + (size_t)kn * HEADD;
            #pragma unroll
            for (int i = 0; i < 4; i++) {
                int c = tid + i * 256;
                int row = c >> 3, cc = c & 7;
                uint32_t off = (uint32_t)((row*SRH + cc*8)*2);
                cpa16(sb + nK + off, Kp + row*HEADD + cc*8);
                cpa16(sb + nV + off, Vp + row*HEADD + cc*8);
            }
        }
        CPA_COMMIT();

        const bool lastc = (ktc == ntc - 1);

        #pragma unroll
        for (int st = 0; st < 2; st++) {
            const int k0s = ktc * 128 + st * 64;
            if (k0s > rowmax) continue;        // fully masked sub-tile
            const uint32_t subK = bufK + (uint32_t)(st * SUBT);
            const uint32_t subV = bufV + (uint32_t)(st * SUBT);

            // S = Q K^T (2-pass)
            float sa[8][4] = {};
            #pragma unroll
            for (int ks = 0; ks < 4; ks++) {
                const uint32_t kb = (uint32_t)(ks * 16 * 2);
                uint32_t bk[4][4];
                #pragma unroll
                for (int p = 0; p < 4; p++)
                    ldmx4(sb + subK + aBoff + p * (16*SRH*2) + kb,
                          bk[p][0], bk[p][1], bk[p][2], bk[p][3]);
                #pragma unroll
                for (int nf = 0; nf < 8; nf++)
                    mma_f16(sa[nf], qh[ks], &bk[nf >> 1][(nf & 1) * 2]);
                #pragma unroll
                for (int nf = 0; nf < 8; nf++)
                    mma_f16(sa[nf], ql[ks], &bk[nf >> 1][(nf & 1) * 2]);
            }

            // Causal mask (only the last chunk overlaps the diagonal)
            if (lastc) {
                const int r0g = q0 + warp*16 + (lane >> 2);
                const int cbase = k0s + (lane & 3) * 2;
                #pragma unroll
                for (int nf = 0; nf < 8; nf++) {
                    const int c0 = cbase + nf*8, c1 = c0 + 1;
                    if (c0 > r0g)     sa[nf][0] = -1e30f;
                    if (c1 > r0g)     sa[nf][1] = -1e30f;
                    if (c0 > r0g + 8) sa[nf][2] = -1e30f;
                    if (c1 > r0g + 8) sa[nf][3] = -1e30f;
                }
            }

            // No-max softmax: P = exp2(s); accumulate row sums
            float ps0 = 0.0f, ps1 = 0.0f;
            #pragma unroll
            for (int nf = 0; nf < 8; nf++) {
                sa[nf][0] = exp2f(sa[nf][0]);
                sa[nf][1] = exp2f(sa[nf][1]);
                sa[nf][2] = exp2f(sa[nf][2]);
                sa[nf][3] = exp2f(sa[nf][3]);
                ps0 += sa[nf][0] + sa[nf][1];
                ps1 += sa[nf][2] + sa[nf][3];
            }
            ps0 += __shfl_xor_sync(0xffffffffu, ps0, 1);
            ps0 += __shfl_xor_sync(0xffffffffu, ps0, 2);
            ps1 += __shfl_xor_sync(0xffffffffu, ps1, 1);
            ps1 += __shfl_xor_sync(0xffffffffu, ps1, 2);
            l0 += ps0;  l1 += ps1;

            // O += P V (single fp16 pass)
            #pragma unroll
            for (int ks = 0; ks < 4; ks++) {
                const uint32_t kb = (uint32_t)(ks * 16 * 2);
                uint32_t vb[4][4];
                #pragma unroll
                for (int p = 0; p < 4; p++)
                    ldmx4t(sb + subV + aVoff + kb * SRH + p * (16*2),
                           vb[p][0], vb[p][1], vb[p][2], vb[p][3]);
                uint32_t ph[4];
                #pragma unroll
                for (int t = 0; t < 2; t++) {
                    const int nf = 2*ks + t;
                    ph[2*t]   = h2u(__floats2half2_rn(sa[nf][0], sa[nf][1]));
                    ph[2*t+1] = h2u(__floats2half2_rn(sa[nf][2], sa[nf][3]));
                }
                #pragma unroll
                for (int nf = 0; nf < 8; nf++)
                    mma_f16(oa[nf], ph, &vb[nf >> 1][(nf & 1) * 2]);
            }
        }
    }

    // Epilogue: normalize, write fp16 C [b, s, h*64+d]
    const float inv0 = 1.0f / l0, inv1 = 1.0f / l1;
    const int m = q0 + warp*16 + (lane >> 2);
    const size_t r0off = ((size_t)b * SEQ + m)     * (NHEADS*HEADD) + h*HEADD;
    const size_t r1off = ((size_t)b * SEQ + m + 8) * (NHEADS*HEADD) + h*HEADD;
    #pragma unroll
    for (int nf = 0; nf < 8; nf++) {
        const int d = nf*8 + (lane & 3)*2;
        *(uint32_t*)&g_C16[r0off + d] = h2u(__floats2half2_rn(oa[nf][0]*inv0, oa[nf][1]*inv0));
        *(uint32_t*)&g_C16[r1off + d] = h2u(__floats2half2_rn(oa[nf][2]*inv1, oa[nf][3]*inv1));
    }
}

// ---------------------------------------------------------------------------
// Kernel 3: output projection — fp16 single-pass, CK=64, 3-stage pipeline.
// ---------------------------------------------------------------------------
__global__ __launch_bounds__(256) void out_proj_mma_kernel(float* __restrict__ outp)
{
    extern __shared__ char smem[];
    const uint32_t sb = smem_u32(smem);
    const int tid = threadIdx.x;
    const int warp = tid >> 5, lane = tid & 31;
    const int wm = warp & 3, wn = warp >> 2;

    const int m0 = blockIdx.x * 128;
    const int n0 = blockIdx.y * 128;

    auto issue = [&](int c, int buf) {
        const uint32_t bb = sb + buf * BUF2;
        const int k0 = c * CK;
        #pragma unroll
        for (int i = 0; i < 4; i++) {
            int idx = i * 256 + tid;
            int q = idx & 7, m = idx >> 3;
            const __half* src = g_C16 + (size_t)(m0 + m) * EMBED + k0 + q * 8;
            cpa16(bb + (uint32_t)((m * SRA + q * 8) * 2), src);
        }
        #pragma unroll
        for (int i = 0; i < 4; i++) {
            int idx = i * 256 + tid;
            int seg = idx & 15, k = idx >> 4;
            const __half* src = g_Wo16 + (size_t)(k0 + k) * EMBED + n0 + seg * 8;
            cpa16(bb + ASZ2 + (uint32_t)((k * SBN + seg * 8) * 2), src);
        }
        CPA_COMMIT();
    };

    float acc[2][8][4] = {};
    const uint32_t aAoff = (uint32_t)(((wm*32 + (lane & 15)) * SRA + (lane >> 4) * 8) * 2);
    const uint32_t bBoff = (uint32_t)(((lane & 15) * SBN + (lane >> 4) * 8) * 2);

    issue(0, 0);
    issue(1, 1);
    int bufc = 0;
    for (int c = 0; c < NC2; c++) {
        CPA_WAIT1();
        __syncthreads();
        if (c + 2 < NC2) issue(c + 2, (c + 2) % 3); else CPA_COMMIT();

        const uint32_t bb = sb + bufc * BUF2;
        bufc = (bufc + 1) % 3;
        #pragma unroll
        for (int ks = 0; ks < 4; ks++) {
            const uint32_t kb = (uint32_t)(ks * 32);
            uint32_t ah[2][4], bf[4][4];
            #pragma unroll
            for (int mi = 0; mi < 2; mi++)
                ldmx4(bb + aAoff + mi*(16*SRA*2) + kb, ah[mi][0], ah[mi][1], ah[mi][2], ah[mi][3]);
            #pragma unroll
            for (int p = 0; p < 4; p++)
                ldmx4t(bb + ASZ2 + (uint32_t)((ks*16*SBN + wn*64 + p*16) * 2) + bBoff,
                       bf[p][0], bf[p][1], bf[p][2], bf[p][3]);
            #pragma unroll
            for (int mi = 0; mi < 2; mi++)
                #pragma unroll
                for (int nj = 0; nj < 8; nj++)
                    mma_f16(acc[mi][nj], ah[mi], &bf[nj >> 1][(nj & 1) * 2]);
        }
    }

    #pragma unroll
    for (int mi = 0; mi < 2; mi++) {
        const int m = m0 + wm*32 + mi*16 + (lane >> 2);
        #pragma unroll
        for (int nj = 0; nj < 8; nj++) {
            const int n = n0 + wn*64 + nj*8 + (lane & 3) * 2;
            *(float2*)&outp[(size_t)m * EMBED + n] = make_float2(acc[mi][nj][0], acc[mi][nj][1]);
            *(float2*)&outp[(size_t)(m + 8) * EMBED + n] = make_float2(acc[mi][nj][2], acc[mi][nj][3]);
        }
    }
}

// ---------------------------------------------------------------------------
extern "C" void kernel_launch(void* const* d_in, const int* in_sizes, int n_in,
                              void* d_out, int out_size)
{
    const float* x  = (const float*)d_in[0];
    const float* Wq = (const float*)d_in[1];
    const float* Wk = (const float*)d_in[2];
    const float* Wv = (const float*)d_in[3];
    const float* Wo = (const float*)d_in[4];
    float* out = (float*)d_out;

    __half *p_x16, *p_Wf, *p_Wo16;
    cudaGetSymbolAddress((void**)&p_x16,  g_x16);
    cudaGetSymbolAddress((void**)&p_Wf,   g_Wf);
    cudaGetSymbolAddress((void**)&p_Wo16, g_Wo16);

    // 0) Pre-convert: 12 segments, 2 float4 per thread
    conv_all_kernel<<<dim3(CONV_SEG/512, 12), 256>>>(
        (const float4*)x, (const float4*)Wq, (const float4*)Wk,
        (const float4*)Wv, (const float4*)Wo, p_x16, p_Wf, p_Wo16);

    // 1) QKV projections (fp16 single-pass, CK=64, 3-stage pipeline)
    cudaFuncSetAttribute(qkv_mma_kernel, cudaFuncAttributeMaxDynamicSharedMemorySize, PROJ_SMEM);
    qkv_mma_kernel<<<dim3(BS/128, NHEADS/2, 3), 256, PROJ_SMEM>>>();

    // 2) Causal flash attention (128-key chunks, 64-key sub-tiles)
    cudaFuncSetAttribute(attn_mma_kernel, cudaFuncAttributeMaxDynamicSharedMemorySize, ATTN_SMEM);
    attn_mma_kernel<<<dim3(SEQ/128, NHEADS, BATCH), 256, ATTN_SMEM>>>();

    // 3) Output projection (fp16 single-pass, CK=64, 3-stage pipeline)
    cudaFuncSetAttribute(out_proj_mma_kernel, cudaFuncAttributeMaxDynamicSharedMemorySize, PROJ_SMEM);
    out_proj_mma_kernel<<<dim3(BS/128, EMBED/128), 256, PROJ_SMEM>>>(out);
}

// round 17
// speedup vs baseline: 1.1362x; 1.1362x over previous
#include <cuda_runtime.h>
#include <cuda_bf16.h>
#include <cuda_fp16.h>
#include <cstdint>
#include <math.h>

// Problem constants
#define NHEADS 16
#define HEADD  64
#define EMBED  1024
#define SEQ    2048
#define BATCH  4
#define BS     (BATCH*SEQ)          // 8192 rows
#define QKV_ELEMS (BATCH*NHEADS*SEQ*HEADD)  // 8388608
#define W_ELEMS (NHEADS*EMBED*HEADD)        // 1048576

#define CK     64                   // K-chunk for projection GEMMs
#define NC2    (EMBED/CK)           // 16 chunks

#define SRA    72                   // A smem row stride (halves): 64 data + 8 pad
#define SBN    136                  // B smem row stride (halves): 128 data + 8 pad

// Q pre-scale: 1/sqrt(64) * log2(e)  (softmax runs in log2 domain)
#define QSCALE 0.180336880111273336f

// Scratch (static device globals: allocation-free)
__device__ __half g_x16[BS*EMBED];          // x fp16
__device__ __half g_Wf[3*W_ELEMS];          // Wq|Wk|Wv fp16
__device__ __half g_Wo16[EMBED*EMBED];      // Wo fp16
__device__ __half g_Q16[QKV_ELEMS];         // Q fp16 (pre-scaled by QSCALE)
__device__ __half g_K16[QKV_ELEMS];         // K fp16
__device__ __half g_V16[QKV_ELEMS];         // V fp16
__device__ __half g_C16[QKV_ELEMS];         // attn output fp16 [B,S,H*D]

// ---------------------------------------------------------------------------
// Common PTX helpers
// ---------------------------------------------------------------------------
__device__ __forceinline__ uint32_t smem_u32(const void* p) {
    uint32_t a;
    asm("{ .reg .u64 t; cvta.to.shared.u64 t, %1; cvt.u32.u64 %0, t; }" : "=r"(a) : "l"(p));
    return a;
}
__device__ __forceinline__ void ldmx4(uint32_t addr, uint32_t& r0, uint32_t& r1,
                                      uint32_t& r2, uint32_t& r3) {
    asm volatile("ldmatrix.sync.aligned.m8n8.x4.shared.b16 {%0,%1,%2,%3}, [%4];"
                 : "=r"(r0), "=r"(r1), "=r"(r2), "=r"(r3) : "r"(addr));
}
__device__ __forceinline__ void ldmx4t(uint32_t addr, uint32_t& r0, uint32_t& r1,
                                       uint32_t& r2, uint32_t& r3) {
    asm volatile("ldmatrix.sync.aligned.m8n8.x4.trans.shared.b16 {%0,%1,%2,%3}, [%4];"
                 : "=r"(r0), "=r"(r1), "=r"(r2), "=r"(r3) : "r"(addr));
}
__device__ __forceinline__ void mma_f16(float* d, const uint32_t* a, const uint32_t* b) {
    asm volatile(
        "mma.sync.aligned.m16n8k16.row.col.f32.f16.f16.f32 "
        "{%0,%1,%2,%3}, {%4,%5,%6,%7}, {%8,%9}, {%0,%1,%2,%3};"
        : "+f"(d[0]), "+f"(d[1]), "+f"(d[2]), "+f"(d[3])
        : "r"(a[0]), "r"(a[1]), "r"(a[2]), "r"(a[3]), "r"(b[0]), "r"(b[1]));
}
__device__ __forceinline__ void cpa16(uint32_t dst, const void* src) {
    asm volatile("cp.async.cg.shared.global [%0], [%1], 16;" :: "r"(dst), "l"(src) : "memory");
}
#define CPA_COMMIT() asm volatile("cp.async.commit_group;" ::: "memory")
#define CPA_WAIT0()  asm volatile("cp.async.wait_group 0;" ::: "memory")
#define CPA_WAIT1()  asm volatile("cp.async.wait_group 1;" ::: "memory")
__device__ __forceinline__ uint32_t h2u(__half2 v) { return *reinterpret_cast<uint32_t*>(&v); }

// ---------------------------------------------------------------------------
// Conversion kernel: z=0..3 -> weights; z=4..11 -> x segments. 2 float4/thread.
// ---------------------------------------------------------------------------
#define CONV_SEG 262144

__global__ __launch_bounds__(256) void conv_all_kernel(
    const float4* __restrict__ x,
    const float4* __restrict__ Wq, const float4* __restrict__ Wk,
    const float4* __restrict__ Wv, const float4* __restrict__ Wo,
    __half* __restrict__ dx, __half* __restrict__ dWf, __half* __restrict__ dWo)
{
    int z = blockIdx.y;
    int i0 = blockIdx.x * 256 + threadIdx.x;
    const float4* src;
    __half* dst;
    if (z < 4) {
        src = (z == 0) ? Wq : (z == 1) ? Wk : (z == 2) ? Wv : Wo;
        dst = (z < 3) ? (dWf + (size_t)z * W_ELEMS) : dWo;
    } else {
        size_t off = (size_t)(z - 4) * CONV_SEG;
        src = x + off;
        dst = dx + off * 4;
    }
    float4 v0 = src[i0];
    float4 v1 = src[i0 + CONV_SEG/2];
    *(uint2*)&dst[(size_t)i0*4] =
        make_uint2(h2u(__floats2half2_rn(v0.x, v0.y)), h2u(__floats2half2_rn(v0.z, v0.w)));
    *(uint2*)&dst[((size_t)i0 + CONV_SEG/2)*4] =
        make_uint2(h2u(__floats2half2_rn(v1.x, v1.y)), h2u(__floats2half2_rn(v1.z, v1.w)));
}

// ---------------------------------------------------------------------------
// Projection GEMM smem layout (CK=64)
// ---------------------------------------------------------------------------
#define ASZ2 (128*SRA*2)            // 18432
#define BSZ2 (64*SBN*2)             // 17408
#define BUF2 (ASZ2 + BSZ2)          // 35840
#define PROJ_SMEM (3*BUF2)          // 107520

// ---------------------------------------------------------------------------
// Kernel 1: fused QKV projection — fp16 single-pass, CK=64, 3-stage pipeline.
// ---------------------------------------------------------------------------
__global__ __launch_bounds__(256) void qkv_mma_kernel()
{
    extern __shared__ char smem[];
    const uint32_t sb = smem_u32(smem);
    const int tid = threadIdx.x;
    const int warp = tid >> 5, lane = tid & 31;
    const int wm = warp & 3, wn = warp >> 2;

    const int z  = blockIdx.z;
    const __half* Wf = g_Wf + (size_t)z * W_ELEMS;
    const int h0 = blockIdx.y * 2;
    const int m0 = blockIdx.x * 128;

    auto issue = [&](int c, int buf) {
        const uint32_t bb = sb + buf * BUF2;
        const int k0 = c * CK;
        #pragma unroll
        for (int i = 0; i < 4; i++) {
            int idx = i * 256 + tid;
            int q = idx & 7, m = idx >> 3;
            const __half* src = g_x16 + (size_t)(m0 + m) * EMBED + k0 + q * 8;
            cpa16(bb + (uint32_t)((m * SRA + q * 8) * 2), src);
        }
        #pragma unroll
        for (int i = 0; i < 4; i++) {
            int idx = i * 256 + tid;
            int seg = idx & 7, h1 = (idx >> 3) & 1, k = idx >> 4;
            const __half* src = Wf + ((size_t)(h0 + h1) * EMBED + k0 + k) * HEADD + seg * 8;
            cpa16(bb + ASZ2 + (uint32_t)((k * SBN + h1 * 64 + seg * 8) * 2), src);
        }
        CPA_COMMIT();
    };

    float acc[2][8][4] = {};
    const uint32_t aAoff = (uint32_t)(((wm*32 + (lane & 15)) * SRA + (lane >> 4) * 8) * 2);
    const uint32_t bBoff = (uint32_t)(((lane & 15) * SBN + (lane >> 4) * 8) * 2);

    issue(0, 0);
    issue(1, 1);
    int bufc = 0;
    for (int c = 0; c < NC2; c++) {
        CPA_WAIT1();
        __syncthreads();
        if (c + 2 < NC2) issue(c + 2, (c + 2) % 3); else CPA_COMMIT();

        const uint32_t bb = sb + bufc * BUF2;
        bufc = (bufc + 1) % 3;
        #pragma unroll
        for (int ks = 0; ks < 4; ks++) {
            const uint32_t kb = (uint32_t)(ks * 32);
            uint32_t ah[2][4], bf[4][4];
            #pragma unroll
            for (int mi = 0; mi < 2; mi++)
                ldmx4(bb + aAoff + mi*(16*SRA*2) + kb, ah[mi][0], ah[mi][1], ah[mi][2], ah[mi][3]);
            #pragma unroll
            for (int p = 0; p < 4; p++)
                ldmx4t(bb + ASZ2 + (uint32_t)((ks*16*SBN + wn*64 + p*16) * 2) + bBoff,
                       bf[p][0], bf[p][1], bf[p][2], bf[p][3]);
            #pragma unroll
            for (int mi = 0; mi < 2; mi++)
                #pragma unroll
                for (int nj = 0; nj < 8; nj++)
                    mma_f16(acc[mi][nj], ah[mi], &bf[nj >> 1][(nj & 1) * 2]);
        }
    }

    // Epilogue: Q scaled single fp16; K/V fp16
    const int h = h0 + wn;
    #pragma unroll
    for (int mi = 0; mi < 2; mi++) {
        const int m = m0 + wm*32 + mi*16 + (lane >> 2);
        const int b = m >> 11, s = m & 2047;
        const size_t rowbase  = (((size_t)b * NHEADS + h) * SEQ + s) * HEADD;
        const size_t rowbase8 = rowbase + 8 * HEADD;
        #pragma unroll
        for (int nj = 0; nj < 8; nj++) {
            const int d = nj*8 + (lane & 3) * 2;
            float a0 = acc[mi][nj][0], a1 = acc[mi][nj][1];
            float a2 = acc[mi][nj][2], a3 = acc[mi][nj][3];
            if (z == 0) {
                a0 *= QSCALE; a1 *= QSCALE; a2 *= QSCALE; a3 *= QSCALE;
                *(uint32_t*)&g_Q16[rowbase  + d] = h2u(__floats2half2_rn(a0, a1));
                *(uint32_t*)&g_Q16[rowbase8 + d] = h2u(__floats2half2_rn(a2, a3));
            } else if (z == 1) {
                *(uint32_t*)&g_K16[rowbase  + d] = h2u(__floats2half2_rn(a0, a1));
                *(uint32_t*)&g_K16[rowbase8 + d] = h2u(__floats2half2_rn(a2, a3));
            } else {
                *(uint32_t*)&g_V16[rowbase  + d] = h2u(__floats2half2_rn(a0, a1));
                *(uint32_t*)&g_V16[rowbase8 + d] = h2u(__floats2half2_rn(a2, a3));
            }
        }
    }
}

// ---------------------------------------------------------------------------
// Kernel 2: causal flash attention (fp16; QK SINGLE-pass, PV 1-pass;
// no-max softmax; Q-in-regs). R13's 64-key double-buffered cadence. 2 CTA/SM.
// ---------------------------------------------------------------------------
#define SRH 72
#define ATTN_SMEM (128*SRH*2 + 4*64*SRH*2)   // Q + K0,K1,V0,V1 = 55296
#define OQ  0
#define OK0 (128*SRH*2)
#define OK1 (OK0 + 64*SRH*2)
#define OV0 (OK1 + 64*SRH*2)
#define OV1 (OV0 + 64*SRH*2)

__global__ __launch_bounds__(256, 2) void attn_mma_kernel()
{
    extern __shared__ char smem[];
    const uint32_t sb = smem_u32(smem);

    const int it = (int)gridDim.x - 1 - (int)blockIdx.x;
    const int h  = blockIdx.y;
    const int b  = blockIdx.z;
    const size_t base = (((size_t)b * NHEADS + h) * SEQ) * HEADD;

    const int tid  = threadIdx.x;
    const int warp = tid >> 5, lane = tid & 31;
    const int q0 = it * 128;
    const int nt = (q0 >> 6) + 2;

    // Prologue: Q (128 rows) + K0/V0 (64 rows each)
    {
        const __half* Qp = g_Q16 + base + (size_t)q0 * HEADD;
        #pragma unroll
        for (int i = 0; i < 4; i++) {
            int c = tid + i * 256;
            int row = c >> 3, cc = c & 7;
            cpa16(sb + OQ + (row*SRH + cc*8)*2, Qp + row*HEADD + cc*8);
        }
        const __half* Kp = g_K16 + base;
        const __half* Vp = g_V16 + base;
        #pragma unroll
        for (int i = 0; i < 2; i++) {
            int c = tid + i * 256;
            int row = c >> 3, cc = c & 7;
            cpa16(sb + OK0 + (row*SRH + cc*8)*2, Kp + row*HEADD + cc*8);
            cpa16(sb + OV0 + (row*SRH + cc*8)*2, Vp + row*HEADD + cc*8);
        }
        CPA_COMMIT();
    }

    float oa[8][4] = {};
    float l0 = 0.0f, l1 = 0.0f;

    const uint32_t aQoff = (uint32_t)(((warp*16 + (lane & 15)) * SRH + (lane >> 4) * 8) * 2);
    const int j = lane >> 3;
    const uint32_t aBoff = (uint32_t)((((j >> 1) * 8 + (lane & 7)) * SRH + (j & 1) * 8) * 2);
    const uint32_t aVoff = (uint32_t)(((lane & 15) * SRH + (lane >> 4) * 8) * 2);
    const int rowmax = q0 + warp*16 + 15;

    // Hoist Q fragments (single tensor) into registers
    uint32_t qh[4][4];
    {
        CPA_WAIT0();
        __syncthreads();
        #pragma unroll
        for (int ks = 0; ks < 4; ks++) {
            const uint32_t kb = (uint32_t)(ks * 16 * 2);
            ldmx4(sb + OQ + aQoff + kb, qh[ks][0], qh[ks][1], qh[ks][2], qh[ks][3]);
        }
    }

    for (int kt = 0; kt < nt; kt++) {
        if (kt > 0) { CPA_WAIT0(); __syncthreads(); }
        const int k0 = kt * 64;
        const uint32_t bufK = (kt & 1) ? OK1 : OK0;
        const uint32_t bufV = (kt & 1) ? OV1 : OV0;

        if (kt + 1 < nt) {
            const int kn = (kt + 1) * 64;
            const uint32_t nK = ((kt + 1) & 1) ? OK1 : OK0;
            const uint32_t nV = ((kt + 1) & 1) ? OV1 : OV0;
            const __half* Kp = g_K16 + base + (size_t)kn * HEADD;
            const __half* Vp = g_V16 + base + (size_t)kn * HEADD;
            #pragma unroll
            for (int i = 0; i < 2; i++) {
                int c = tid + i * 256;
                int row = c >> 3, cc = c & 7;
                cpa16(sb + nK + (row*SRH + cc*8)*2, Kp + row*HEADD + cc*8);
                cpa16(sb + nV + (row*SRH + cc*8)*2, Vp + row*HEADD + cc*8);
            }
        }
        CPA_COMMIT();

        if (k0 > rowmax) continue;

        // S = Q K^T (single pass)
        float sa[8][4] = {};
        #pragma unroll
        for (int ks = 0; ks < 4; ks++) {
            const uint32_t kb = (uint32_t)(ks * 16 * 2);
            uint32_t bk[4][4];
            #pragma unroll
            for (int p = 0; p < 4; p++)
                ldmx4(sb + bufK + aBoff + p * (16*SRH*2) + kb,
                      bk[p][0], bk[p][1], bk[p][2], bk[p][3]);
            #pragma unroll
            for (int nf = 0; nf < 8; nf++)
                mma_f16(sa[nf], qh[ks], &bk[nf >> 1][(nf & 1) * 2]);
        }

        // Causal mask near the diagonal
        if (kt >= nt - 2) {
            const int r0g = q0 + warp*16 + (lane >> 2);
            const int cbase = k0 + (lane & 3) * 2;
            #pragma unroll
            for (int nf = 0; nf < 8; nf++) {
                const int c0 = cbase + nf*8, c1 = c0 + 1;
                if (c0 > r0g)     sa[nf][0] = -1e30f;
                if (c1 > r0g)     sa[nf][1] = -1e30f;
                if (c0 > r0g + 8) sa[nf][2] = -1e30f;
                if (c1 > r0g + 8) sa[nf][3] = -1e30f;
            }
        }

        // No-max softmax: P = exp2(s); accumulate row sums
        float ps0 = 0.0f, ps1 = 0.0f;
        #pragma unroll
        for (int nf = 0; nf < 8; nf++) {
            sa[nf][0] = exp2f(sa[nf][0]);
            sa[nf][1] = exp2f(sa[nf][1]);
            sa[nf][2] = exp2f(sa[nf][2]);
            sa[nf][3] = exp2f(sa[nf][3]);
            ps0 += sa[nf][0] + sa[nf][1];
            ps1 += sa[nf][2] + sa[nf][3];
        }
        ps0 += __shfl_xor_sync(0xffffffffu, ps0, 1);
        ps0 += __shfl_xor_sync(0xffffffffu, ps0, 2);
        ps1 += __shfl_xor_sync(0xffffffffu, ps1, 1);
        ps1 += __shfl_xor_sync(0xffffffffu, ps1, 2);
        l0 += ps0;  l1 += ps1;

        // O += P V (single fp16 pass)
        #pragma unroll
        for (int ks = 0; ks < 4; ks++) {
            const uint32_t kb = (uint32_t)(ks * 16 * 2);
            uint32_t vb[4][4];
            #pragma unroll
            for (int p = 0; p < 4; p++)
                ldmx4t(sb + bufV + aVoff + kb * SRH + p * (16*2),
                       vb[p][0], vb[p][1], vb[p][2], vb[p][3]);
            uint32_t ph[4];
            #pragma unroll
            for (int t = 0; t < 2; t++) {
                const int nf = 2*ks + t;
                ph[2*t]   = h2u(__floats2half2_rn(sa[nf][0], sa[nf][1]));
                ph[2*t+1] = h2u(__floats2half2_rn(sa[nf][2], sa[nf][3]));
            }
            #pragma unroll
            for (int nf = 0; nf < 8; nf++)
                mma_f16(oa[nf], ph, &vb[nf >> 1][(nf & 1) * 2]);
        }
    }

    // Epilogue: normalize, write fp16 C [b, s, h*64+d]
    const float inv0 = 1.0f / l0, inv1 = 1.0f / l1;
    const int m = q0 + warp*16 + (lane >> 2);
    const size_t r0off = ((size_t)b * SEQ + m)     * (NHEADS*HEADD) + h*HEADD;
    const size_t r1off = ((size_t)b * SEQ + m + 8) * (NHEADS*HEADD) + h*HEADD;
    #pragma unroll
    for (int nf = 0; nf < 8; nf++) {
        const int d = nf*8 + (lane & 3)*2;
        *(uint32_t*)&g_C16[r0off + d] = h2u(__floats2half2_rn(oa[nf][0]*inv0, oa[nf][1]*inv0));
        *(uint32_t*)&g_C16[r1off + d] = h2u(__floats2half2_rn(oa[nf][2]*inv1, oa[nf][3]*inv1));
    }
}

// ---------------------------------------------------------------------------
// Kernel 3: output projection — fp16 single-pass, CK=64, 3-stage pipeline.
// ---------------------------------------------------------------------------
__global__ __launch_bounds__(256) void out_proj_mma_kernel(float* __restrict__ outp)
{
    extern __shared__ char smem[];
    const uint32_t sb = smem_u32(smem);
    const int tid = threadIdx.x;
    const int warp = tid >> 5, lane = tid & 31;
    const int wm = warp & 3, wn = warp >> 2;

    const int m0 = blockIdx.x * 128;
    const int n0 = blockIdx.y * 128;

    auto issue = [&](int c, int buf) {
        const uint32_t bb = sb + buf * BUF2;
        const int k0 = c * CK;
        #pragma unroll
        for (int i = 0; i < 4; i++) {
            int idx = i * 256 + tid;
            int q = idx & 7, m = idx >> 3;
            const __half* src = g_C16 + (size_t)(m0 + m) * EMBED + k0 + q * 8;
            cpa16(bb + (uint32_t)((m * SRA + q * 8) * 2), src);
        }
        #pragma unroll
        for (int i = 0; i < 4; i++) {
            int idx = i * 256 + tid;
            int seg = idx & 15, k = idx >> 4;
            const __half* src = g_Wo16 + (size_t)(k0 + k) * EMBED + n0 + seg * 8;
            cpa16(bb + ASZ2 + (uint32_t)((k * SBN + seg * 8) * 2), src);
        }
        CPA_COMMIT();
    };

    float acc[2][8][4] = {};
    const uint32_t aAoff = (uint32_t)(((wm*32 + (lane & 15)) * SRA + (lane >> 4) * 8) * 2);
    const uint32_t bBoff = (uint32_t)(((lane & 15) * SBN + (lane >> 4) * 8) * 2);

    issue(0, 0);
    issue(1, 1);
    int bufc = 0;
    for (int c = 0; c < NC2; c++) {
        CPA_WAIT1();
        __syncthreads();
        if (c + 2 < NC2) issue(c + 2, (c + 2) % 3); else CPA_COMMIT();

        const uint32_t bb = sb + bufc * BUF2;
        bufc = (bufc + 1) % 3;
        #pragma unroll
        for (int ks = 0; ks < 4; ks++) {
            const uint32_t kb = (uint32_t)(ks * 32);
            uint32_t ah[2][4], bf[4][4];
            #pragma unroll
            for (int mi = 0; mi < 2; mi++)
                ldmx4(bb + aAoff + mi*(16*SRA*2) + kb, ah[mi][0], ah[mi][1], ah[mi][2], ah[mi][3]);
            #pragma unroll
            for (int p = 0; p < 4; p++)
                ldmx4t(bb + ASZ2 + (uint32_t)((ks*16*SBN + wn*64 + p*16) * 2) + bBoff,
                       bf[p][0], bf[p][1], bf[p][2], bf[p][3]);
            #pragma unroll
            for (int mi = 0; mi < 2; mi++)
                #pragma unroll
                for (int nj = 0; nj < 8; nj++)
                    mma_f16(acc[mi][nj], ah[mi], &bf[nj >> 1][(nj & 1) * 2]);
        }
    }

    #pragma unroll
    for (int mi = 0; mi < 2; mi++) {
        const int m = m0 + wm*32 + mi*16 + (lane >> 2);
        #pragma unroll
        for (int nj = 0; nj < 8; nj++) {
            const int n = n0 + wn*64 + nj*8 + (lane & 3) * 2;
            *(float2*)&outp[(size_t)m * EMBED + n] = make_float2(acc[mi][nj][0], acc[mi][nj][1]);
            *(float2*)&outp[(size_t)(m + 8) * EMBED + n] = make_float2(acc[mi][nj][2], acc[mi][nj][3]);
        }
    }
}

// ---------------------------------------------------------------------------
extern "C" void kernel_launch(void* const* d_in, const int* in_sizes, int n_in,
                              void* d_out, int out_size)
{
    const float* x  = (const float*)d_in[0];
    const float* Wq = (const float*)d_in[1];
    const float* Wk = (const float*)d_in[2];
    const float* Wv = (const float*)d_in[3];
    const float* Wo = (const float*)d_in[4];
    float* out = (float*)d_out;

    __half *p_x16, *p_Wf, *p_Wo16;
    cudaGetSymbolAddress((void**)&p_x16,  g_x16);
    cudaGetSymbolAddress((void**)&p_Wf,   g_Wf);
    cudaGetSymbolAddress((void**)&p_Wo16, g_Wo16);

    // 0) Pre-convert: 12 segments, 2 float4 per thread
    conv_all_kernel<<<dim3(CONV_SEG/512, 12), 256>>>(
        (const float4*)x, (const float4*)Wq, (const float4*)Wk,
        (const float4*)Wv, (const float4*)Wo, p_x16, p_Wf, p_Wo16);

    // 1) QKV projections (fp16 single-pass, CK=64, 3-stage pipeline)
    cudaFuncSetAttribute(qkv_mma_kernel, cudaFuncAttributeMaxDynamicSharedMemorySize, PROJ_SMEM);
    qkv_mma_kernel<<<dim3(BS/128, NHEADS/2, 3), 256, PROJ_SMEM>>>();

    // 2) Causal flash attention (QK single-pass, PV single-pass, no-max)
    cudaFuncSetAttribute(attn_mma_kernel, cudaFuncAttributeMaxDynamicSharedMemorySize, ATTN_SMEM);
    attn_mma_kernel<<<dim3(SEQ/128, NHEADS, BATCH), 256, ATTN_SMEM>>>();

    // 3) Output projection (fp16 single-pass, CK=64, 3-stage pipeline)
    cudaFuncSetAttribute(out_proj_mma_kernel, cudaFuncAttributeMaxDynamicSharedMemorySize, PROJ_SMEM);
    out_proj_mma_kernel<<<dim3(BS/128, EMBED/128), 256, PROJ_SMEM>>>(out);
}